// round 6
// baseline (speedup 1.0000x reference)
#include <cuda_runtime.h>

#define NN   50000
#define DD   64
#define OUTN 16
#define EE   800000
#define SCB  256
#define GEMM_TILE 64
#define NB_GEMM ((NN + GEMM_TILE - 1) / GEMM_TILE)   // 782

// ---------------- static device scratch ----------------
__device__ int   g_deg_out[NN];
__device__ int   g_deg_in[NN];
__device__ float g_norm_src[NN];
__device__ float g_norm_dst[NN];
__device__ int   g_rowptr[NN + 1];
__device__ int   g_cursor[NN];
__device__ int   g_col[EE];
__device__ float g_xs[NN * DD];    // norm_src-prescaled activations (SpMM input)
__device__ float g_agg[NN * DD];   // SpMM output / GEMM input
__device__ float g_partial[NB_GEMM * OUTN];

// ---------------- edge degree histogram (deg arrays zero on entry; re-zeroed
// by k_scatter_scale so the invariant holds across graph replays) -------------
__global__ void k_count(const int* __restrict__ src, const int* __restrict__ dst, int e) {
    int i = blockIdx.x * blockDim.x + threadIdx.x;
    if (i < e) {
        atomicAdd(&g_deg_out[src[i]], 1);
        atomicAdd(&g_deg_in[dst[i]], 1);
    }
}

// ---------------- fused scan + norm ------------------------------------------
__global__ void k_scan_norm(int n, int e) {
    __shared__ int red[SCB];
    int b = blockIdx.x, t = threadIdx.x;
    int start = b * SCB;

    int s = 0;
    for (int i = t; i < start; i += SCB) s += g_deg_in[i];
    red[t] = s;
    __syncthreads();
    for (int off = 128; off > 0; off >>= 1) {
        if (t < off) red[t] += red[t + off];
        __syncthreads();
    }
    int base = red[0];
    __syncthreads();

    int i = start + t;
    int v = (i < n) ? g_deg_in[i] : 0;
    red[t] = v;
    __syncthreads();
    for (int off = 1; off < SCB; off <<= 1) {
        int u = (t >= off) ? red[t - off] : 0;
        __syncthreads();
        red[t] += u;
        __syncthreads();
    }
    int ex = base + red[t] - v;
    if (i < n) {
        g_rowptr[i] = ex;
        g_cursor[i] = ex;
        g_norm_src[i] = rsqrtf((float)(g_deg_out[i] + 1));
        g_norm_dst[i] = rsqrtf((float)(v + 1));
    }
    if (b == 0 && t == 0) g_rowptr[n] = e;
}

// ---------------- CSR scatter + F prescale + deg re-zero ----------------------
__global__ void k_scatter_scale(const int* __restrict__ src, const int* __restrict__ dst,
                                const float* __restrict__ F, int e, int n) {
    int i = blockIdx.x * blockDim.x + threadIdx.x;
    if (i < e) {
        int d = dst[i];
        int pos = atomicAdd(&g_cursor[d], 1);
        g_col[pos] = src[i];
    }
    if (i < n) { g_deg_in[i] = 0; g_deg_out[i] = 0; }
    if (i < n * (DD / 4)) {
        int node = i >> 4;
        float ns = g_norm_src[node];
        float4 v = ((const float4*)F)[i];
        v.x *= ns; v.y *= ns; v.z *= ns; v.w *= ns;
        ((float4*)g_xs)[i] = v;
    }
}

// ---------------- SpMM: agg[n] = norm_dst[n] * (xs[n] + sum_in xs[s]) ----------
// Warp per node. Edge indices preloaded 32-at-a-time (one coalesced LDG per
// lane) and broadcast via shfl; main body = 16 edges/iter = 8 in-flight float4
// gathers per half-warp.
__global__ void k_spmm(const float* __restrict__ xs, float* __restrict__ agg, int n) {
    int gw = (blockIdx.x * blockDim.x + threadIdx.x) >> 5;
    if (gw >= n) return;
    int lane = threadIdx.x & 31;
    int half = lane >> 4;
    int q    = lane & 15;

    int rs = g_rowptr[gw];
    int deg = g_rowptr[gw + 1] - rs;

    float4 acc;
    if (half == 0) acc = ((const float4*)(xs + (size_t)gw * DD))[q];   // self loop
    else           acc = make_float4(0.f, 0.f, 0.f, 0.f);

    for (int base = 0; base < deg; base += 32) {
        int idx = base + lane;
        int c = (idx < deg) ? g_col[rs + idx] : 0;
        int m = deg - base; if (m > 32) m = 32;

        int j = 0;
        for (; j + 16 <= m; j += 16) {
            int s0 = __shfl_sync(0xffffffffu, c, j + half + 0);
            int s1 = __shfl_sync(0xffffffffu, c, j + half + 2);
            int s2 = __shfl_sync(0xffffffffu, c, j + half + 4);
            int s3 = __shfl_sync(0xffffffffu, c, j + half + 6);
            int s4 = __shfl_sync(0xffffffffu, c, j + half + 8);
            int s5 = __shfl_sync(0xffffffffu, c, j + half + 10);
            int s6 = __shfl_sync(0xffffffffu, c, j + half + 12);
            int s7 = __shfl_sync(0xffffffffu, c, j + half + 14);
            float4 v0 = ((const float4*)(xs + (size_t)s0 * DD))[q];
            float4 v1 = ((const float4*)(xs + (size_t)s1 * DD))[q];
            float4 v2 = ((const float4*)(xs + (size_t)s2 * DD))[q];
            float4 v3 = ((const float4*)(xs + (size_t)s3 * DD))[q];
            float4 v4 = ((const float4*)(xs + (size_t)s4 * DD))[q];
            float4 v5 = ((const float4*)(xs + (size_t)s5 * DD))[q];
            float4 v6 = ((const float4*)(xs + (size_t)s6 * DD))[q];
            float4 v7 = ((const float4*)(xs + (size_t)s7 * DD))[q];
            acc.x += (v0.x + v1.x) + (v2.x + v3.x) + ((v4.x + v5.x) + (v6.x + v7.x));
            acc.y += (v0.y + v1.y) + (v2.y + v3.y) + ((v4.y + v5.y) + (v6.y + v7.y));
            acc.z += (v0.z + v1.z) + (v2.z + v3.z) + ((v4.z + v5.z) + (v6.z + v7.z));
            acc.w += (v0.w + v1.w) + (v2.w + v3.w) + ((v4.w + v5.w) + (v6.w + v7.w));
        }
        for (; j + 2 <= m; j += 2) {
            int s0 = __shfl_sync(0xffffffffu, c, j + half);
            float4 v0 = ((const float4*)(xs + (size_t)s0 * DD))[q];
            acc.x += v0.x; acc.y += v0.y; acc.z += v0.z; acc.w += v0.w;
        }
        if (j < m) {
            int s0 = __shfl_sync(0xffffffffu, c, j);
            if (half == 0) {
                float4 v0 = ((const float4*)(xs + (size_t)s0 * DD))[q];
                acc.x += v0.x; acc.y += v0.y; acc.z += v0.z; acc.w += v0.w;
            }
        }
    }

    acc.x += __shfl_xor_sync(0xffffffffu, acc.x, 16);
    acc.y += __shfl_xor_sync(0xffffffffu, acc.y, 16);
    acc.z += __shfl_xor_sync(0xffffffffu, acc.z, 16);
    acc.w += __shfl_xor_sync(0xffffffffu, acc.w, 16);

    if (half == 0) {
        float nd = g_norm_dst[gw];
        acc.x *= nd; acc.y *= nd; acc.z *= nd; acc.w *= nd;
        ((float4*)(agg + (size_t)gw * DD))[q] = acc;
    }
}

// ---------------- dense layers 0/1: xs = relu(agg @ W + b) * norm_src -----------
__global__ void k_gemm(const float* __restrict__ agg, float* __restrict__ xout,
                       const float* __restrict__ W, const float* __restrict__ B, int n) {
    __shared__ float sW[DD * DD];
    __shared__ float sB[DD];
    __shared__ float sA[GEMM_TILE * DD];

    int tid = threadIdx.x;
    for (int i = tid; i < DD * DD; i += 256) sW[i] = W[i];
    if (tid < DD) sB[tid] = B[tid];

    int base = blockIdx.x * GEMM_TILE;
    int gmax = n * (DD / 4);
    for (int i = tid; i < GEMM_TILE * (DD / 4); i += 256) {
        int gi = base * (DD / 4) + i;
        float4 v = (gi < gmax) ? ((const float4*)agg)[gi] : make_float4(0.f, 0.f, 0.f, 0.f);
        ((float4*)sA)[i] = v;
    }
    __syncthreads();

    int j  = tid & 31;
    int sg = tid >> 5;

    float acc0[8], acc1[8];
#pragma unroll
    for (int m = 0; m < 8; m++) { acc0[m] = sB[j]; acc1[m] = sB[j + 32]; }

#pragma unroll
    for (int k4 = 0; k4 < DD / 4; k4++) {
        float w0[4], w1[4];
#pragma unroll
        for (int kk = 0; kk < 4; kk++) {
            w0[kk] = sW[(k4 * 4 + kk) * DD + j];
            w1[kk] = sW[(k4 * 4 + kk) * DD + j + 32];
        }
#pragma unroll
        for (int m = 0; m < 8; m++) {
            float4 a = ((const float4*)(sA + (sg * 8 + m) * DD))[k4];
            acc0[m] += a.x * w0[0] + a.y * w0[1] + a.z * w0[2] + a.w * w0[3];
            acc1[m] += a.x * w1[0] + a.y * w1[1] + a.z * w1[2] + a.w * w1[3];
        }
    }

#pragma unroll
    for (int m = 0; m < 8; m++) {
        int node = base + sg * 8 + m;
        if (node < n) {
            float sc = g_norm_src[node];
            xout[(size_t)node * DD + j]      = fmaxf(acc0[m], 0.f) * sc;
            xout[(size_t)node * DD + j + 32] = fmaxf(acc1[m], 0.f) * sc;
        }
    }
}

// ---------------- fused layer-2 GEMM + FC partial --------------------------------
// Computes relu(agg @ W + b) for a 64-node tile entirely in registers, then
// immediately dots it against the 16 matching fc_w slices (coalesced), writing
// 16 per-block partial sums. The 205MB fc_w stream overlaps the GEMM FMAs and
// the x roundtrip through memory disappears.
__global__ void k_gemm_fc(const float* __restrict__ agg,
                          const float* __restrict__ W, const float* __restrict__ B,
                          const float* __restrict__ fcw, int n) {
    __shared__ float sW[DD * DD];
    __shared__ float sB[DD];
    __shared__ float sA[GEMM_TILE * DD];
    __shared__ float sRed[8 * OUTN];

    int tid = threadIdx.x;
    for (int i = tid; i < DD * DD; i += 256) sW[i] = W[i];
    if (tid < DD) sB[tid] = B[tid];

    int base = blockIdx.x * GEMM_TILE;
    int gmax = n * (DD / 4);
    for (int i = tid; i < GEMM_TILE * (DD / 4); i += 256) {
        int gi = base * (DD / 4) + i;
        float4 v = (gi < gmax) ? ((const float4*)agg)[gi] : make_float4(0.f, 0.f, 0.f, 0.f);
        ((float4*)sA)[i] = v;
    }
    __syncthreads();

    int j  = tid & 31;
    int sg = tid >> 5;

    float acc0[8], acc1[8];
#pragma unroll
    for (int m = 0; m < 8; m++) { acc0[m] = sB[j]; acc1[m] = sB[j + 32]; }

#pragma unroll
    for (int k4 = 0; k4 < DD / 4; k4++) {
        float w0[4], w1[4];
#pragma unroll
        for (int kk = 0; kk < 4; kk++) {
            w0[kk] = sW[(k4 * 4 + kk) * DD + j];
            w1[kk] = sW[(k4 * 4 + kk) * DD + j + 32];
        }
#pragma unroll
        for (int m = 0; m < 8; m++) {
            float4 a = ((const float4*)(sA + (sg * 8 + m) * DD))[k4];
            acc0[m] += a.x * w0[0] + a.y * w0[1] + a.z * w0[2] + a.w * w0[3];
            acc1[m] += a.x * w1[0] + a.y * w1[1] + a.z * w1[2] + a.w * w1[3];
        }
    }

    // relu in place; mask out-of-range nodes
#pragma unroll
    for (int m = 0; m < 8; m++) {
        int node = base + sg * 8 + m;
        bool ok = (node < n);
        acc0[m] = ok ? fmaxf(acc0[m], 0.f) : 0.f;
        acc1[m] = ok ? fmaxf(acc1[m], 0.f) : 0.f;
    }

    // FC epilogue: for each of 16 outputs, dot this thread's 16 flat elements
    // against fc_w. Lanes (j=0..31) produce coalesced 128B loads.
    size_t nd = (size_t)n * DD;
#pragma unroll
    for (int j2 = 0; j2 < OUTN; j2++) {
        const float* wrow = fcw + (size_t)j2 * nd + (size_t)base * DD;
        float s = 0.f;
#pragma unroll
        for (int m = 0; m < 8; m++) {
            int node = base + sg * 8 + m;
            if (node < n) {
                const float* wp = wrow + (sg * 8 + m) * DD;
                s += wp[j] * acc0[m] + wp[j + 32] * acc1[m];
            }
        }
        // warp reduce
#pragma unroll
        for (int o = 16; o > 0; o >>= 1) s += __shfl_xor_sync(0xffffffffu, s, o);
        if (j == 0) sRed[sg * OUTN + j2] = s;
    }
    __syncthreads();

    if (tid < OUTN) {
        float s = 0.f;
#pragma unroll
        for (int w = 0; w < 8; w++) s += sRed[w * OUTN + tid];
        g_partial[blockIdx.x * OUTN + tid] = s;
    }
}

// ---------------- FC final reduction (fixed order, deterministic) ----------------
__global__ void k_fc_final(float* __restrict__ out, const float* __restrict__ fcb, int nb) {
    int j = threadIdx.x >> 5;
    int lane = threadIdx.x & 31;
    if (j < OUTN) {
        float s = 0.f;
        for (int b = lane; b < nb; b += 32) s += g_partial[b * OUTN + j];
#pragma unroll
        for (int o = 16; o > 0; o >>= 1) s += __shfl_down_sync(0xffffffffu, s, o);
        if (lane == 0) out[j] = s + fcb[j];
    }
}

// ---------------- launcher --------------------------------------------------------
extern "C" void kernel_launch(void* const* d_in, const int* in_sizes, int n_in,
                              void* d_out, int out_size) {
    const float* F     = (const float*)d_in[0];
    const int*   src   = (const int*)d_in[1];
    const int*   dst   = (const int*)d_in[2];
    const float* gcn_w = (const float*)d_in[3];
    const float* gcn_b = (const float*)d_in[4];
    const float* fc_w  = (const float*)d_in[5];
    const float* fc_b  = (const float*)d_in[6];
    float* out = (float*)d_out;

    int n = in_sizes[0] / DD;
    int e = in_sizes[1];

    float *xs, *agg;
    cudaGetSymbolAddress((void**)&xs,  g_xs);
    cudaGetSymbolAddress((void**)&agg, g_agg);

    int nb_e = (e + 255) / 256;
    int nb_scan = (n + SCB - 1) / SCB;
    int spmm_blocks = (n * 32 + 255) / 256;
    int gemm_blocks = (n + GEMM_TILE - 1) / GEMM_TILE;

    // graph build (3 launches)
    k_count<<<nb_e, 256>>>(src, dst, e);
    k_scan_norm<<<nb_scan, SCB>>>(n, e);
    k_scatter_scale<<<nb_e, 256>>>(src, dst, F, e, n);

    // layer 0
    k_spmm<<<spmm_blocks, 256>>>(xs, agg, n);     // launch #4 (profiled)
    k_gemm<<<gemm_blocks, 256>>>(agg, xs, gcn_w + 0 * DD * DD, gcn_b + 0 * DD, n);
    // layer 1
    k_spmm<<<spmm_blocks, 256>>>(xs, agg, n);
    k_gemm<<<gemm_blocks, 256>>>(agg, xs, gcn_w + 1 * DD * DD, gcn_b + 1 * DD, n);
    // layer 2 fused with FC partial
    k_spmm<<<spmm_blocks, 256>>>(xs, agg, n);
    k_gemm_fc<<<gemm_blocks, 256>>>(agg, gcn_w + 2 * DD * DD, gcn_b + 2 * DD, fc_w, n);

    // FC final
    k_fc_final<<<1, OUTN * 32>>>(out, fc_b, gemm_blocks);
}